// round 3
// baseline (speedup 1.0000x reference)
#include <cuda_runtime.h>
#include <math.h>

// Problem constants
#define NB   128      // batch
#define NT   512      // seq len
#define ND   512      // input size
#define NH   1024     // hidden size
#define NG   4096     // 4*NH packed gate columns (i,f,o,c interleaved per unit)
#define NOUT 512      // output size

// ---------------- device scratch (static allocations only) ----------------
__device__ float g_Wx[ND * NG];                 //  8 MB : Wx[k][4j+g]
__device__ float g_Wh[NH * NG];                 // 16 MB : Wh[k][4j+g]
__device__ float g_bias[NG];
__device__ float g_Gx[268435456];               //  1 GB : [t*128+b][4096]
__device__ float g_h[2][NB * NH];               // ping-pong hidden state
__device__ float g_c[NB * NH];                  // cell state (in-place)

// ---------------------------------------------------------------------------
// Pack weights into gate-interleaved layout: col 4j+0=i, +1=f, +2=o, +3=c~
// ---------------------------------------------------------------------------
__global__ void pack_kernel(const float* __restrict__ Wi, const float* __restrict__ Wf,
                            const float* __restrict__ Wo, const float* __restrict__ Wc,
                            const float* __restrict__ bi, const float* __restrict__ bf,
                            const float* __restrict__ bo, const float* __restrict__ bc) {
    int idx = blockIdx.x * blockDim.x + threadIdx.x;
    if (idx < 1536 * NH) {
        int k = idx >> 10;          // row in [0,1536)
        int j = idx & 1023;         // hidden unit
        float vi = Wi[idx], vf = Wf[idx], vo = Wo[idx], vc = Wc[idx];
        if (k < ND) {
            float* dst = &g_Wx[(size_t)k * NG + 4 * j];
            dst[0] = vi; dst[1] = vf; dst[2] = vo; dst[3] = vc;
        } else {
            float* dst = &g_Wh[(size_t)(k - ND) * NG + 4 * j];
            dst[0] = vi; dst[1] = vf; dst[2] = vo; dst[3] = vc;
        }
    }
    if (idx < NH) {
        g_bias[4 * idx + 0] = bi[idx];
        g_bias[4 * idx + 1] = bf[idx];
        g_bias[4 * idx + 2] = bo[idx];
        g_bias[4 * idx + 3] = bc[idx];
    }
}

__global__ void init_kernel() {
    int i = blockIdx.x * blockDim.x + threadIdx.x;
    if (i < NB * NH) {
        g_h[0][i] = 0.f;
        g_h[1][i] = 0.f;
        g_c[i]    = 0.f;
    }
}

// ---------------------------------------------------------------------------
// Gx = X @ Wx + bias   (M=65536 rows indexed m = t*128+b, K=512, N=4096)
// Classic 128x128x8 sgemm, 256 threads, 8x8 microtile.
// ---------------------------------------------------------------------------
__global__ void __launch_bounds__(256) gx_kernel(const float* __restrict__ x) {
    __shared__ float As[8][128];   // As[k][m]
    __shared__ float Bs[8][128];   // Bs[k][n]

    const int tid = threadIdx.x;
    const int tx  = tid & 15;      // N microtile index
    const int ty  = tid >> 4;      // M microtile index
    const int m0  = blockIdx.y * 128;
    const int n0  = blockIdx.x * 128;

    // A loader: 128 rows x 2 float4 per row
    const int arow  = tid >> 1;
    const int ahalf = (tid & 1) * 4;
    const int gm    = m0 + arow;                        // m = t*128 + b
    const float* xrow = x + ((size_t)(gm & 127) * NT + (gm >> 7)) * ND;
    // B loader: 8 k-rows x 32 float4 per row
    const int bk = tid >> 5;
    const int bn = (tid & 31) * 4;

    float acc[8][8];
#pragma unroll
    for (int i = 0; i < 8; i++)
#pragma unroll
        for (int j = 0; j < 8; j++) acc[i][j] = 0.f;

    for (int kt = 0; kt < ND; kt += 8) {
        float4 av = *(const float4*)(xrow + kt + ahalf);
        float4 bv = *(const float4*)(&g_Wx[(size_t)(kt + bk) * NG + n0 + bn]);
        __syncthreads();
        As[ahalf + 0][arow] = av.x;
        As[ahalf + 1][arow] = av.y;
        As[ahalf + 2][arow] = av.z;
        As[ahalf + 3][arow] = av.w;
        *(float4*)&Bs[bk][bn] = bv;
        __syncthreads();
#pragma unroll
        for (int k = 0; k < 8; k++) {
            float a[8], b[8];
            *(float4*)&a[0] = *(const float4*)&As[k][ty * 8];
            *(float4*)&a[4] = *(const float4*)&As[k][ty * 8 + 4];
            *(float4*)&b[0] = *(const float4*)&Bs[k][tx * 8];
            *(float4*)&b[4] = *(const float4*)&Bs[k][tx * 8 + 4];
#pragma unroll
            for (int i = 0; i < 8; i++)
#pragma unroll
                for (int j = 0; j < 8; j++) acc[i][j] += a[i] * b[j];
        }
    }

#pragma unroll
    for (int i = 0; i < 8; i++) {
        int gm2 = m0 + ty * 8 + i;
        float* crow = &g_Gx[(size_t)gm2 * NG + n0 + tx * 8];
#pragma unroll
        for (int j = 0; j < 8; j++) crow[j] = acc[i][j] + g_bias[n0 + tx * 8 + j];
    }
}

// ---------------------------------------------------------------------------
// One LSTM step: gates = Gx[t] + h_in @ Wh, then fused nonlinearity + update.
// Tile 64x64, K=1024 in 16-deep k-tiles (half the barriers of 8-deep),
// 128 threads, 8x4 microtile (4 cols = one hidden unit's gates).
// grid = (64, 2)
// ---------------------------------------------------------------------------
__device__ __forceinline__ float sigf(float v) { return 1.f / (1.f + expf(-v)); }

__global__ void __launch_bounds__(128) step_kernel(int t) {
    __shared__ float As[16][64];   // As[k][m]  (h rows)
    __shared__ float Bs[16][64];   // Bs[k][n]  (Wh cols)

    const float* __restrict__ h_in  = g_h[t & 1];
    float*       __restrict__ h_out = g_h[(t + 1) & 1];
    const float* __restrict__ Gxt   = &g_Gx[(size_t)t * NB * NG];

    const int tid = threadIdx.x;
    const int tx  = tid & 15;      // 16 col-groups (4 cols each)
    const int ty  = tid >> 4;      // 8 row-groups (8 rows each)
    const int n0  = blockIdx.x * 64;
    const int m0  = blockIdx.y * 64;

    // A loader: 64 rows x 16 k -> 2 threads/row, 2 float4 each
    const int arow = tid >> 1;
    const int aoff = (tid & 1) * 8;        // k offset 0 or 8
    // B loader: 16 k-rows x 64 n -> rows bkk and bkk+8, 1 float4 each
    const int bkk  = tid >> 4;             // 0..7
    const int bnn  = (tid & 15) * 4;       // 0..60

    float4 acc[8];
#pragma unroll
    for (int r = 0; r < 8; r++)
        acc[r] = *(const float4*)(Gxt + (size_t)(m0 + ty * 8 + r) * NG + n0 + tx * 4);

    const float* arowp = h_in + (size_t)(m0 + arow) * NH;

    for (int kt = 0; kt < NH; kt += 16) {
        float4 a0 = *(const float4*)(arowp + kt + aoff);
        float4 a1 = *(const float4*)(arowp + kt + aoff + 4);
        float4 b0 = *(const float4*)(&g_Wh[(size_t)(kt + bkk)     * NG + n0 + bnn]);
        float4 b1 = *(const float4*)(&g_Wh[(size_t)(kt + bkk + 8) * NG + n0 + bnn]);
        __syncthreads();
        As[aoff + 0][arow] = a0.x;
        As[aoff + 1][arow] = a0.y;
        As[aoff + 2][arow] = a0.z;
        As[aoff + 3][arow] = a0.w;
        As[aoff + 4][arow] = a1.x;
        As[aoff + 5][arow] = a1.y;
        As[aoff + 6][arow] = a1.z;
        As[aoff + 7][arow] = a1.w;
        *(float4*)&Bs[bkk][bnn]     = b0;
        *(float4*)&Bs[bkk + 8][bnn] = b1;
        __syncthreads();
#pragma unroll
        for (int k = 0; k < 16; k++) {
            float4 b = *(const float4*)&Bs[k][tx * 4];
            float a[8];
            *(float4*)&a[0] = *(const float4*)&As[k][ty * 8];
            *(float4*)&a[4] = *(const float4*)&As[k][ty * 8 + 4];
#pragma unroll
            for (int r = 0; r < 8; r++) {
                acc[r].x += a[r] * b.x;
                acc[r].y += a[r] * b.y;
                acc[r].z += a[r] * b.z;
                acc[r].w += a[r] * b.w;
            }
        }
    }

    // fused LSTM update: this thread owns hidden unit j for 8 batch rows
    const int j = (n0 >> 2) + tx;
#pragma unroll
    for (int r = 0; r < 8; r++) {
        int bb = m0 + ty * 8 + r;
        float ig = sigf(acc[r].x);
        float fg = sigf(acc[r].y);
        float og = sigf(acc[r].z);
        float cg = tanhf(acc[r].w);
        float c  = fg * g_c[bb * NH + j] + ig * cg;
        g_c[bb * NH + j]  = c;
        h_out[bb * NH + j] = og * tanhf(c);
    }
}

// ---------------------------------------------------------------------------
// Output projection: out = [h, c] @ W_out + b_out   (M=128, K=2048, N=512)
// Tile 64x64, 128 threads, 8x4 microtile. grid = (8, 2)
// ---------------------------------------------------------------------------
__global__ void __launch_bounds__(128) out_kernel(const float* __restrict__ Wout,
                                                  const float* __restrict__ bout,
                                                  float* __restrict__ out) {
    __shared__ float As[8][64];
    __shared__ float Bs[8][64];

    const int tid = threadIdx.x;
    const int tx  = tid & 15;
    const int ty  = tid >> 4;
    const int n0  = blockIdx.x * 64;
    const int m0  = blockIdx.y * 64;

    const int arow  = tid >> 1;
    const int ahalf = (tid & 1) * 4;
    const int bkk   = tid >> 4;
    const int bnn   = (tid & 15) * 4;

    float4 acc[8];
#pragma unroll
    for (int r = 0; r < 8; r++) acc[r] = make_float4(0.f, 0.f, 0.f, 0.f);

    for (int kt = 0; kt < 2 * NH; kt += 8) {
        int k = kt + ahalf;
        const float* asrc = (k < NH)
            ? &g_h[0][(size_t)(m0 + arow) * NH + k]
            : &g_c[(size_t)(m0 + arow) * NH + (k - NH)];
        float4 av = *(const float4*)asrc;
        float4 bv = *(const float4*)(&Wout[(size_t)(kt + bkk) * NOUT + n0 + bnn]);
        __syncthreads();
        As[ahalf + 0][arow] = av.x;
        As[ahalf + 1][arow] = av.y;
        As[ahalf + 2][arow] = av.z;
        As[ahalf + 3][arow] = av.w;
        *(float4*)&Bs[bkk][bnn] = bv;
        __syncthreads();
#pragma unroll
        for (int k2 = 0; k2 < 8; k2++) {
            float4 b = *(const float4*)&Bs[k2][tx * 4];
            float a[8];
            *(float4*)&a[0] = *(const float4*)&As[k2][ty * 8];
            *(float4*)&a[4] = *(const float4*)&As[k2][ty * 8 + 4];
#pragma unroll
            for (int r = 0; r < 8; r++) {
                acc[r].x += a[r] * b.x;
                acc[r].y += a[r] * b.y;
                acc[r].z += a[r] * b.z;
                acc[r].w += a[r] * b.w;
            }
        }
    }

#pragma unroll
    for (int r = 0; r < 8; r++) {
        int bb = m0 + ty * 8 + r;
        int nn = n0 + tx * 4;
        float4 o = acc[r];
        o.x += bout[nn + 0];
        o.y += bout[nn + 1];
        o.z += bout[nn + 2];
        o.w += bout[nn + 3];
        *(float4*)&out[(size_t)bb * NOUT + nn] = o;
    }
}

// Copy final h into the second region of the output buffer
__global__ void copyh_kernel(float* __restrict__ out) {
    int i = blockIdx.x * blockDim.x + threadIdx.x;
    if (i < NB * NH) out[NB * NOUT + i] = g_h[0][i];
}

// ---------------------------------------------------------------------------
extern "C" void kernel_launch(void* const* d_in, const int* in_sizes, int n_in,
                              void* d_out, int out_size) {
    const float* x    = (const float*)d_in[0];
    const float* Wi   = (const float*)d_in[1];
    const float* bi   = (const float*)d_in[2];
    const float* Wf   = (const float*)d_in[3];
    const float* bf   = (const float*)d_in[4];
    const float* Wo   = (const float*)d_in[5];
    const float* bo   = (const float*)d_in[6];
    const float* Wc   = (const float*)d_in[7];
    const float* bc   = (const float*)d_in[8];
    const float* Wout = (const float*)d_in[9];
    const float* bout = (const float*)d_in[10];
    float* out = (float*)d_out;

    pack_kernel<<<(1536 * NH + 255) / 256, 256>>>(Wi, Wf, Wo, Wc, bi, bf, bo, bc);
    init_kernel<<<(NB * NH + 255) / 256, 256>>>();
    gx_kernel<<<dim3(NG / 128, (NT * NB) / 128), 256>>>(x);
    for (int t = 0; t < NT; t++)
        step_kernel<<<dim3(NG / 64, NB / 64), 128>>>(t);
    out_kernel<<<dim3(NOUT / 64, NB / 64), 128>>>(Wout, bout, out);
    copyh_kernel<<<(NB * NH + 255) / 256, 256>>>(out);
}

// round 5
// speedup vs baseline: 1.5509x; 1.5509x over previous
#include <cuda_runtime.h>
#include <math.h>
#include <stdint.h>

// Problem constants
#define NB   128      // batch
#define NT   512      // seq len
#define ND   512      // input size
#define NH   1024     // hidden size
#define NG   4096     // packed gate columns
#define NOUT 512      // output size

// Gate column packing: for unit j (g16 = j>>2, u = j&3) within 16-col group:
//   col(i) = g16*16 + 2u, col(f) = +1, col(o) = g16*16 + 8 + 2u, col(c~) = +9
// K (hidden-unit) permutation for tf32 fragment vectorization:
//   pi(k) = (k & ~15) | ((k&3)<<2) | ((k>>2)&3)
__device__ __forceinline__ int kperm(int k) {
    return (k & ~15) | ((k & 3) << 2) | ((k >> 2) & 3);
}

// ---------------- device scratch (static allocations only) ----------------
__device__ float g_Wx[ND * NG];                 //  8 MB fp32 [k][packed n]
__device__ float g_Wht[(size_t)NG * NH];        // 16 MB tf32 bits, [packed n][pi(k)]
__device__ float g_bias[NG];
__device__ float g_Gx[268435456];               //  1 GB : [t*128+b][packed n]
__device__ float g_h[2][NB * NH];               // h at [b][pi(j)], fp32
__device__ float g_c[NB * NH];                  // c at [b][pi(j)], fp32
__device__ float g_hlin[NB * NH];               // un-permuted h
__device__ float g_clin[NB * NH];               // un-permuted c

__device__ __forceinline__ uint32_t f2tf32(float f) {
    uint32_t r;
    asm("cvt.rna.tf32.f32 %0, %1;" : "=r"(r) : "f"(f));
    return r;
}

__device__ __forceinline__ void mma_tf32(float4& d,
                                         uint32_t a0, uint32_t a1, uint32_t a2, uint32_t a3,
                                         uint32_t b0, uint32_t b1) {
    asm volatile(
        "mma.sync.aligned.m16n8k8.row.col.f32.tf32.tf32.f32 "
        "{%0,%1,%2,%3},{%4,%5,%6,%7},{%8,%9},{%0,%1,%2,%3};"
        : "+f"(d.x), "+f"(d.y), "+f"(d.z), "+f"(d.w)
        : "r"(a0), "r"(a1), "r"(a2), "r"(a3), "r"(b0), "r"(b1));
}

// ---------------------------------------------------------------------------
// Pack weights: Wx fp32 gate-pair packed; Wh transposed, K-permuted, tf32.
// ---------------------------------------------------------------------------
__global__ void pack_kernel(const float* __restrict__ Wi, const float* __restrict__ Wf,
                            const float* __restrict__ Wo, const float* __restrict__ Wc,
                            const float* __restrict__ bi, const float* __restrict__ bf,
                            const float* __restrict__ bo, const float* __restrict__ bc) {
    int idx = blockIdx.x * blockDim.x + threadIdx.x;
    if (idx < 1536 * NH) {
        int k = idx >> 10;          // row in [0,1536)
        int j = idx & 1023;         // hidden unit
        int g16 = j >> 2, u = j & 3;
        int ci = g16 * 16 + 2 * u;
        int cf = ci + 1;
        int co = g16 * 16 + 8 + 2 * u;
        int cc = co + 1;
        float vi = Wi[idx], vf = Wf[idx], vo = Wo[idx], vc = Wc[idx];
        if (k < ND) {
            g_Wx[(size_t)k * NG + ci] = vi;
            g_Wx[(size_t)k * NG + cf] = vf;
            g_Wx[(size_t)k * NG + co] = vo;
            g_Wx[(size_t)k * NG + cc] = vc;
        } else {
            int pk = kperm(k - ND);
            g_Wht[(size_t)ci * NH + pk] = __uint_as_float(f2tf32(vi));
            g_Wht[(size_t)cf * NH + pk] = __uint_as_float(f2tf32(vf));
            g_Wht[(size_t)co * NH + pk] = __uint_as_float(f2tf32(vo));
            g_Wht[(size_t)cc * NH + pk] = __uint_as_float(f2tf32(vc));
        }
    }
    if (idx < NH) {
        int g16 = idx >> 2, u = idx & 3;
        g_bias[g16 * 16 + 2 * u]     = bi[idx];
        g_bias[g16 * 16 + 2 * u + 1] = bf[idx];
        g_bias[g16 * 16 + 8 + 2 * u]     = bo[idx];
        g_bias[g16 * 16 + 8 + 2 * u + 1] = bc[idx];
    }
}

__global__ void init_kernel() {
    int i = blockIdx.x * blockDim.x + threadIdx.x;
    if (i < NB * NH) {
        g_h[0][i] = 0.f;
        g_h[1][i] = 0.f;
        g_c[i]    = 0.f;
    }
}

// ---------------------------------------------------------------------------
// Gx = X @ Wx + bias (fp32): M=65536, K=512, N=4096
// ---------------------------------------------------------------------------
__global__ void __launch_bounds__(256) gx_kernel(const float* __restrict__ x) {
    __shared__ float As[8][128];
    __shared__ float Bs[8][128];

    const int tid = threadIdx.x;
    const int tx  = tid & 15;
    const int ty  = tid >> 4;
    const int m0  = blockIdx.y * 128;
    const int n0  = blockIdx.x * 128;

    const int arow  = tid >> 1;
    const int ahalf = (tid & 1) * 4;
    const int gm    = m0 + arow;
    const float* xrow = x + ((size_t)(gm & 127) * NT + (gm >> 7)) * ND;
    const int bk = tid >> 5;
    const int bn = (tid & 31) * 4;

    float acc[8][8];
#pragma unroll
    for (int i = 0; i < 8; i++)
#pragma unroll
        for (int j = 0; j < 8; j++) acc[i][j] = 0.f;

    for (int kt = 0; kt < ND; kt += 8) {
        float4 av = *(const float4*)(xrow + kt + ahalf);
        float4 bv = *(const float4*)(&g_Wx[(size_t)(kt + bk) * NG + n0 + bn]);
        __syncthreads();
        As[ahalf + 0][arow] = av.x;
        As[ahalf + 1][arow] = av.y;
        As[ahalf + 2][arow] = av.z;
        As[ahalf + 3][arow] = av.w;
        *(float4*)&Bs[bk][bn] = bv;
        __syncthreads();
#pragma unroll
        for (int k = 0; k < 8; k++) {
            float a[8], b[8];
            *(float4*)&a[0] = *(const float4*)&As[k][ty * 8];
            *(float4*)&a[4] = *(const float4*)&As[k][ty * 8 + 4];
            *(float4*)&b[0] = *(const float4*)&Bs[k][tx * 8];
            *(float4*)&b[4] = *(const float4*)&Bs[k][tx * 8 + 4];
#pragma unroll
            for (int i = 0; i < 8; i++)
#pragma unroll
                for (int j = 0; j < 8; j++) acc[i][j] += a[i] * b[j];
        }
    }

#pragma unroll
    for (int i = 0; i < 8; i++) {
        int gm2 = m0 + ty * 8 + i;
        float* crow = &g_Gx[(size_t)gm2 * NG + n0 + tx * 8];
#pragma unroll
        for (int j = 0; j < 8; j++) crow[j] = acc[i][j] + g_bias[n0 + tx * 8 + j];
    }
}

// ---------------------------------------------------------------------------
// LSTM step via tf32 tensor cores.
// gates = Gx[t] + h @ Wh, fused sigmoid/tanh + c/h update in epilogue.
// Block: 64(M=batch) x 64(N=gates), 256 threads, 8 warps (2x4),
// warp tile 32x16 = 2x2 m16n8k8 frags. K=1024 in 16 chunks of 64.
// grid = (64, 2) = 128 blocks.
// ---------------------------------------------------------------------------
__device__ __forceinline__ float sigf(float v) { return 1.f / (1.f + expf(-v)); }

__global__ void __launch_bounds__(256, 1) step_kernel(int t) {
    __shared__ uint32_t As[64][80];   // h tile   [m][k-storage], pad 80
    __shared__ uint32_t Bs[64][80];   // Wh tile  [n][k-storage], pad 80

    const float* __restrict__ h_in  = g_h[t & 1];
    float*       __restrict__ h_out = g_h[(t + 1) & 1];
    const float* __restrict__ Gxt   = g_Gx + (size_t)t * NB * NG;

    const int tid  = threadIdx.x;
    const int lane = tid & 31;
    const int warp = tid >> 5;
    const int wm   = warp >> 2;      // 0..1  (M)
    const int wn   = warp & 3;       // 0..3  (N)
    const int gid  = lane >> 2;      // 0..7
    const int tig  = lane & 3;       // 0..3
    const int m0   = blockIdx.y * 64;
    const int n0   = blockIdx.x * 64;

    // Init accumulators from exact fp32 Gx.
    // acc[mf][nf] = (c0,c1,c2,c3) = (row, 2c), (row, 2c+1), (row+8, 2c), (row+8, 2c+1)
    float4 acc[2][2];
#pragma unroll
    for (int mf = 0; mf < 2; mf++)
#pragma unroll
        for (int nf = 0; nf < 2; nf++) {
            int R    = m0 + wm * 32 + mf * 16 + gid;
            int ncol = n0 + wn * 16 + nf * 8 + 2 * tig;
            float2 lo = *(const float2*)(Gxt + (size_t)R * NG + ncol);
            float2 hi = *(const float2*)(Gxt + (size_t)(R + 8) * NG + ncol);
            acc[mf][nf] = make_float4(lo.x, lo.y, hi.x, hi.y);
        }

    // loaders: each thread owns 16 consecutive floats of one row per chunk
    const int lrow = tid >> 2;          // 0..63
    const int lq   = (tid & 3) * 16;    // 0,16,32,48
    const float* pa = h_in  + (size_t)(m0 + lrow) * NH + lq;
    const float* pb = g_Wht + (size_t)(n0 + lrow) * NH + lq;

    float4 ra[4], rb[4];
#pragma unroll
    for (int i = 0; i < 4; i++) {
        ra[i] = *(const float4*)(pa + 4 * i);
        rb[i] = *(const float4*)(pb + 4 * i);
    }

    for (int kt = 0; kt < NH; kt += 64) {
        __syncthreads();   // prior compute finished reading smem
#pragma unroll
        for (int i = 0; i < 4; i++) {
            *(uint4*)&As[lrow][lq + 4 * i] = make_uint4(
                f2tf32(ra[i].x), f2tf32(ra[i].y), f2tf32(ra[i].z), f2tf32(ra[i].w));
            *(uint4*)&Bs[lrow][lq + 4 * i] = make_uint4(
                __float_as_uint(rb[i].x), __float_as_uint(rb[i].y),
                __float_as_uint(rb[i].z), __float_as_uint(rb[i].w));
        }
        __syncthreads();
        if (kt + 64 < NH) {
#pragma unroll
            for (int i = 0; i < 4; i++) {
                ra[i] = *(const float4*)(pa + kt + 64 + 4 * i);
                rb[i] = *(const float4*)(pb + kt + 64 + 4 * i);
            }
        }
        // 4 k16 windows per chunk; each window = two k8 mma steps
#pragma unroll
        for (int w = 0; w < 4; w++) {
            const int kc = w * 16 + tig * 4;
            uint4 vb0 = *(const uint4*)&Bs[wn * 16 + gid][kc];       // nf=0
            uint4 vb1 = *(const uint4*)&Bs[wn * 16 + 8 + gid][kc];   // nf=1
#pragma unroll
            for (int mf = 0; mf < 2; mf++) {
                uint4 va0 = *(const uint4*)&As[wm * 32 + mf * 16 + gid][kc];
                uint4 va1 = *(const uint4*)&As[wm * 32 + mf * 16 + 8 + gid][kc];
                mma_tf32(acc[mf][0], va0.x, va1.x, va0.y, va1.y, vb0.x, vb0.y);
                mma_tf32(acc[mf][0], va0.z, va1.z, va0.w, va1.w, vb0.z, vb0.w);
                mma_tf32(acc[mf][1], va0.x, va1.x, va0.y, va1.y, vb1.x, vb1.y);
                mma_tf32(acc[mf][1], va0.z, va1.z, va0.w, va1.w, vb1.z, vb1.w);
            }
        }
    }

    // Epilogue: thread owns unit j for 4 batch rows (mf x row-half).
    // nf=0 frag = (i,f), nf=1 frag = (o,c~) of the same unit.
    const int j  = (blockIdx.x * 4 + wn) * 4 + tig;
    const int pj = kperm(j);
#pragma unroll
    for (int mf = 0; mf < 2; mf++) {
        int R0 = m0 + wm * 32 + mf * 16 + gid;
        {
            float ig = sigf(acc[mf][0].x);
            float fg = sigf(acc[mf][0].y);
            float og = sigf(acc[mf][1].x);
            float ct = tanhf(acc[mf][1].y);
            size_t ci = (size_t)R0 * NH + pj;
            float c = fg * g_c[ci] + ig * ct;
            g_c[ci]  = c;
            h_out[ci] = og * tanhf(c);
        }
        {
            float ig = sigf(acc[mf][0].z);
            float fg = sigf(acc[mf][0].w);
            float og = sigf(acc[mf][1].z);
            float ct = tanhf(acc[mf][1].w);
            size_t ci = (size_t)(R0 + 8) * NH + pj;
            float c = fg * g_c[ci] + ig * ct;
            g_c[ci]  = c;
            h_out[ci] = og * tanhf(c);
        }
    }
}

// Un-permute h and c into linear [b][j] layout for the output projection.
__global__ void unperm_kernel() {
    int i = blockIdx.x * blockDim.x + threadIdx.x;
    if (i < NB * NH) {
        int b = i >> 10, j = i & 1023;
        int pj = kperm(j);
        g_hlin[i] = g_h[0][b * NH + pj];
        g_clin[i] = g_c[b * NH + pj];
    }
}

// ---------------------------------------------------------------------------
// Output projection: out = [h, c] @ W_out + b_out   (M=128, K=2048, N=512)
// ---------------------------------------------------------------------------
__global__ void __launch_bounds__(128) out_kernel(const float* __restrict__ Wout,
                                                  const float* __restrict__ bout,
                                                  float* __restrict__ out) {
    __shared__ float As[8][64];
    __shared__ float Bs[8][64];

    const int tid = threadIdx.x;
    const int tx  = tid & 15;
    const int ty  = tid >> 4;
    const int n0  = blockIdx.x * 64;
    const int m0  = blockIdx.y * 64;

    const int arow  = tid >> 1;
    const int ahalf = (tid & 1) * 4;
    const int bkk   = tid >> 4;
    const int bnn   = (tid & 15) * 4;

    float4 acc[8];
#pragma unroll
    for (int r = 0; r < 8; r++) acc[r] = make_float4(0.f, 0.f, 0.f, 0.f);

    for (int kt = 0; kt < 2 * NH; kt += 8) {
        int k = kt + ahalf;
        const float* asrc = (k < NH)
            ? &g_hlin[(size_t)(m0 + arow) * NH + k]
            : &g_clin[(size_t)(m0 + arow) * NH + (k - NH)];
        float4 av = *(const float4*)asrc;
        float4 bv = *(const float4*)(&Wout[(size_t)(kt + bkk) * NOUT + n0 + bnn]);
        __syncthreads();
        As[ahalf + 0][arow] = av.x;
        As[ahalf + 1][arow] = av.y;
        As[ahalf + 2][arow] = av.z;
        As[ahalf + 3][arow] = av.w;
        *(float4*)&Bs[bkk][bnn] = bv;
        __syncthreads();
#pragma unroll
        for (int k2 = 0; k2 < 8; k2++) {
            float4 b = *(const float4*)&Bs[k2][tx * 4];
            float a[8];
            *(float4*)&a[0] = *(const float4*)&As[k2][ty * 8];
            *(float4*)&a[4] = *(const float4*)&As[k2][ty * 8 + 4];
#pragma unroll
            for (int r = 0; r < 8; r++) {
                acc[r].x += a[r] * b.x;
                acc[r].y += a[r] * b.y;
                acc[r].z += a[r] * b.z;
                acc[r].w += a[r] * b.w;
            }
        }
    }

#pragma unroll
    for (int r = 0; r < 8; r++) {
        int bb = m0 + ty * 8 + r;
        int nn = n0 + tx * 4;
        float4 o = acc[r];
        o.x += bout[nn + 0];
        o.y += bout[nn + 1];
        o.z += bout[nn + 2];
        o.w += bout[nn + 3];
        *(float4*)&out[(size_t)bb * NOUT + nn] = o;
    }
}

__global__ void copyh_kernel(float* __restrict__ out) {
    int i = blockIdx.x * blockDim.x + threadIdx.x;
    if (i < NB * NH) out[NB * NOUT + i] = g_hlin[i];
}

// ---------------------------------------------------------------------------
extern "C" void kernel_launch(void* const* d_in, const int* in_sizes, int n_in,
                              void* d_out, int out_size) {
    const float* x    = (const float*)d_in[0];
    const float* Wi   = (const float*)d_in[1];
    const float* bi   = (const float*)d_in[2];
    const float* Wf   = (const float*)d_in[3];
    const float* bf   = (const float*)d_in[4];
    const float* Wo   = (const float*)d_in[5];
    const float* bo   = (const float*)d_in[6];
    const float* Wc   = (const float*)d_in[7];
    const float* bc   = (const float*)d_in[8];
    const float* Wout = (const float*)d_in[9];
    const float* bout = (const float*)d_in[10];
    float* out = (float*)d_out;

    pack_kernel<<<(1536 * NH + 255) / 256, 256>>>(Wi, Wf, Wo, Wc, bi, bf, bo, bc);
    init_kernel<<<(NB * NH + 255) / 256, 256>>>();
    gx_kernel<<<dim3(NG / 128, (NT * NB) / 128), 256>>>(x);
    for (int t = 0; t < NT; t++)
        step_kernel<<<dim3(NG / 64, NB / 64), 256>>>(t);
    unperm_kernel<<<(NB * NH + 255) / 256, 256>>>();
    out_kernel<<<dim3(NOUT / 64, NB / 64), 128>>>(Wout, bout, out);
    copyh_kernel<<<(NB * NH + 255) / 256, 256>>>(out);
}